// round 1
// baseline (speedup 1.0000x reference)
#include <cuda_runtime.h>

// newPad2d: replicate (edge) pad, width 2 on H and W.
// in:  (32, 256, 56, 56) fp32   -> 8192 planes of 56x56
// out: (32, 256, 60, 60) fp32   -> 8192 planes of 60x60
//
// Output row = 60 floats = 240 bytes = 15 aligned float4.
// One thread per output float4: fully coalesced 16B stores.
// Reads: 4 clamped scalar loads per thread; interior loads are consecutive
// addresses so the L1 sectorizer coalesces them.

#define IN_H   56
#define IN_W   56
#define OUT_H  60
#define OUT_W  60
#define PAD    2
#define PLANE_IN   (IN_H * IN_W)      // 3136
#define VEC_PER_ROW (OUT_W / 4)       // 15
#define VEC_PER_PLANE (OUT_H * VEC_PER_ROW)  // 900

__global__ __launch_bounds__(256)
void pad2d_edge_kernel(const float* __restrict__ x,
                       float4* __restrict__ out,
                       int nvec)
{
    int idx = blockIdx.x * blockDim.x + threadIdx.x;
    if (idx >= nvec) return;

    int plane = idx / VEC_PER_PLANE;
    int rem   = idx - plane * VEC_PER_PLANE;
    int h     = rem / VEC_PER_ROW;
    int w0    = (rem - h * VEC_PER_ROW) * 4;   // first output column of this vec

    int hin = min(max(h - PAD, 0), IN_H - 1);
    const float* row = x + (size_t)plane * PLANE_IN + (size_t)hin * IN_W;

    float4 v;
    v.x = row[min(max(w0 - 2, 0), IN_W - 1)];
    v.y = row[min(max(w0 - 1, 0), IN_W - 1)];
    v.z = row[min(max(w0    , 0), IN_W - 1)];
    v.w = row[min(max(w0 + 1, 0), IN_W - 1)];

    out[idx] = v;
}

extern "C" void kernel_launch(void* const* d_in, const int* in_sizes, int n_in,
                              void* d_out, int out_size)
{
    const float* x = (const float*)d_in[0];
    float4* out = (float4*)d_out;

    int nvec = out_size / 4;  // 29,491,200 / 4 = 7,372,800
    int threads = 256;
    int blocks = (nvec + threads - 1) / threads;
    pad2d_edge_kernel<<<blocks, threads>>>(x, out, nvec);
}

// round 2
// speedup vs baseline: 1.0526x; 1.0526x over previous
#include <cuda_runtime.h>

// newPad2d: replicate (edge) pad, width 2 on H and W.
// in:  (32, 256, 56, 56) fp32 -> 8192 planes of 56x56
// out: (32, 256, 60, 60) fp32 -> 8192 planes of 60x60
//
// Each thread produces ILP=4 output float4s, strided 256 apart inside a
// 1024-vec block chunk: stores stay warp-coalesced, and the 16 input LDGs
// are independent and front-batched (MLP ~16/thread) to hide DRAM latency.
// nvec = 7,372,800 = 7200 * 1024 exactly -> no tail handling.

#define IN_H   56
#define IN_W   56
#define OUT_W  60
#define PAD    2
#define PLANE_IN      (IN_H * IN_W)          // 3136
#define VEC_PER_ROW   (OUT_W / 4)            // 15
#define VEC_PER_PLANE (60 * VEC_PER_ROW)     // 900
#define ILP 4
#define THREADS 256
#define CHUNK (THREADS * ILP)                // 1024

__global__ __launch_bounds__(THREADS)
void pad2d_edge_ilp4(const float* __restrict__ x,
                     float4* __restrict__ out)
{
    const int base = blockIdx.x * CHUNK + threadIdx.x;

    const float* rowp[ILP];
    int w0[ILP];

#pragma unroll
    for (int k = 0; k < ILP; k++) {
        int idx   = base + k * THREADS;
        int plane = idx / VEC_PER_PLANE;                 // const-div -> mul/shift
        int rem   = idx - plane * VEC_PER_PLANE;
        int h     = rem / VEC_PER_ROW;
        w0[k]     = (rem - h * VEC_PER_ROW) * 4;
        int hin   = min(max(h - PAD, 0), IN_H - 1);
        rowp[k]   = x + (size_t)plane * PLANE_IN + hin * IN_W;
    }

    float4 v[ILP];
#pragma unroll
    for (int k = 0; k < ILP; k++) {
        const float* row = rowp[k];
        int w = w0[k];
        v[k].x = row[min(max(w - 2, 0), IN_W - 1)];
        v[k].y = row[min(max(w - 1, 0), IN_W - 1)];
        v[k].z = row[min(w,              IN_W - 1)];   // w >= 0 always
        v[k].w = row[min(w + 1,          IN_W - 1)];
    }

#pragma unroll
    for (int k = 0; k < ILP; k++)
        out[base + k * THREADS] = v[k];
}

extern "C" void kernel_launch(void* const* d_in, const int* in_sizes, int n_in,
                              void* d_out, int out_size)
{
    const float* x = (const float*)d_in[0];
    float4* out = (float4*)d_out;

    int nvec = out_size / 4;            // 7,372,800
    int blocks = nvec / CHUNK;          // 7200 exactly
    pad2d_edge_ilp4<<<blocks, THREADS>>>(x, out);
}